// round 11
// baseline (speedup 1.0000x reference)
#include <cuda_runtime.h>

#define B_TOT 4096
#define T_LEN 512
#define D_IN  5
#define NB    28          // batches per CTA (slot space 32: 8+8+6+6; slots 22,23,30,31 unused)
#define GRID  147         // ceil(4096/28), single wave
#define NTHR  512         // warps 0-7: layer0, warps 8-15: layer1
#define HS    36          // padded row stride (floats) for h/x state

// shared memory layout (float offsets) — identical to R10
#define OFF_WHH0 0
#define OFF_WIH1 16384
#define OFF_WHH1 32768
#define OFF_WIH0 49152                 // 5*64*4 = 1280
#define OFF_B0A  (49152 + 1280)        // h0 buffer 0: 64*36 = 2304
#define OFF_B0B  (OFF_B0A + 2304)      // h0 buffer 1
#define OFF_H1   (OFF_B0B + 2304)
#define OFF_XA   (OFF_H1 + 2304)       // 5*36 = 180
#define OFF_XB   (OFF_XA + 180)
#define SMEM_FLOATS (OFF_XB + 180)     // 57,704 floats
#define SMEM_BYTES  (SMEM_FLOATS * 4)  // 230,816 B (boot-proven)

// named barriers (R9/R10-proven protocol)
#define BAR_READY0 1
#define BAR_READY1 2
#define BAR_FREE0  3
#define BAR_FREE1  4
#define BAR_L1INT  7

#define BSYNC(id, cnt) asm volatile("bar.sync %0, %1;" :: "n"(id), "n"(cnt) : "memory")
#define BARRV(id, cnt) asm volatile("bar.arrive %0, %1;" :: "n"(id), "n"(cnt) : "memory")

typedef unsigned long long u64;

union F2U { float2 f; u64 u; };

__device__ __forceinline__ u64 dup2(float x) {
    F2U t; t.f = make_float2(x, x); return t.u;
}
__device__ __forceinline__ float2 unpk(u64 v) { F2U t; t.u = v; return t.f; }

__device__ __forceinline__ void fma2(u64& a, u64 x, u64 w) {
    asm("fma.rn.f32x2 %0, %1, %2, %0;" : "+l"(a) : "l"(x), "l"(w));
}

// MUFU.TANH (validated: rel_err ~7e-7)
__device__ __forceinline__ float tanha(float x) {
    float y; asm("tanh.approx.f32 %0, %1;" : "=f"(y) : "f"(x)); return y;
}
__device__ __forceinline__ float sigf(float x) {
    return fmaf(0.5f, tanha(0.5f * x), 0.5f);
}

// load NA u64 batch-pairs from state row (16B-aligned base; NA=3 tail is 8B-aligned)
template<int NA>
__device__ __forceinline__ void load_pairs(const float* base, u64* hv) {
    ulonglong2 a = *(const ulonglong2*)base;
    hv[0] = a.x; hv[1] = a.y;
    if (NA == 4) {
        ulonglong2 b = *(const ulonglong2*)(base + 4);
        hv[2] = b.x; hv[3] = b.y;
    } else {
        hv[2] = *(const u64*)(base + 4);
    }
}

template<int NA>
__device__ __forceinline__ void store_h(float* dst, const float* hn) {
    *(float4*)dst = make_float4(hn[0], hn[1], hn[2], hn[3]);
    if (NA == 4) *(float4*)(dst + 4) = make_float4(hn[4], hn[5], hn[6], hn[7]);
    else         *(float2*)(dst + 4) = make_float2(hn[4], hn[5]);
}

// one 64-k gate GEMV accumulation pass
template<int NA>
__device__ __forceinline__ void gemvK(const float* __restrict__ W,
                                      const float* __restrict__ hsrc,
                                      int j, int bb,
                                      u64* aI, u64* aF, u64* aG, u64* aO)
{
#pragma unroll 4
    for (int k = 0; k < 64; k++) {
        float4 w = *(const float4*)&W[(k * 64 + j) * 4];
        u64 wi = dup2(w.x), wf = dup2(w.y), wg = dup2(w.z), wo = dup2(w.w);
        u64 hv[4];
        load_pairs<NA>(&hsrc[k * HS + bb], hv);
#pragma unroll
        for (int i = 0; i < NA; i++) {
            fma2(aI[i], hv[i], wi); fma2(aF[i], hv[i], wf);
            fma2(aG[i], hv[i], wg); fma2(aO[i], hv[i], wo);
        }
    }
}

template<int NA>
__device__ __forceinline__ void pointwiseN(const u64* aI, const u64* aF,
                                           const u64* aG, const u64* aO,
                                           float* c, float* hn)
{
#pragma unroll
    for (int p = 0; p < NA; p++) {
        float2 vi = unpk(aI[p]), vf = unpk(aF[p]), vg = unpk(aG[p]), vo = unpk(aO[p]);
        float ca = sigf(vf.x) * c[2 * p]     + sigf(vi.x) * tanha(vg.x);
        float cb = sigf(vf.y) * c[2 * p + 1] + sigf(vi.y) * tanha(vg.y);
        c[2 * p] = ca; c[2 * p + 1] = cb;
        hn[2 * p]     = sigf(vo.x) * tanha(ca);
        hn[2 * p + 1] = sigf(vo.y) * tanha(cb);
    }
}

// ===================== LAYER 0 GROUP body =====================
template<int NA>
__device__ __forceinline__ void run_layer0(
    const float* wih0, const float* whh0,
    float* bufA, float* bufB, float* xsA, float* xsB,
    const float* __restrict__ x,
    const float* __restrict__ b_ih0, const float* __restrict__ b_hh0,
    int j, int bb, int B0, int tid)
{
    const u64 bi0 = dup2(b_ih0[j]       + b_hh0[j]);
    const u64 bf0 = dup2(b_ih0[64 + j]  + b_hh0[64 + j]);
    const u64 bg0 = dup2(b_ih0[128 + j] + b_hh0[128 + j]);
    const u64 bo0 = dup2(b_ih0[192 + j] + b_hh0[192 + j]);
    float c0[2 * NA];
#pragma unroll
    for (int p = 0; p < 2 * NA; p++) c0[p] = 0.0f;

    // x staging: threads 0..139 own (local batch l, feature xd); slot map skips 22,23
    const int l  = tid / 5;
    const int xd = tid - l * 5;
    int gb = B0 + l; if (gb > B_TOT - 1) gb = B_TOT - 1;   // edge-CTA clamp
    const int xslot = l + (l >= 22 ? 2 : 0);
    const float* xptr = x + (size_t)gb * (T_LEN * D_IN) + xd;
    float xreg = 0.0f;
    if (tid < 140) {
        xsA[xd * HS + xslot] = xptr[0];   // stage x[0]
        xreg = xptr[D_IN];                // prefetch x[1]
    }

    for (int t = 0; t < T_LEN; t++) {
        const int p = t & 1;
        float* bw = p ? bufB : bufA;        // write h0[t]
        const float* br = p ? bufA : bufB;  // read h0[t-1]
        const float* xc = p ? xsB : xsA;

        if (p) { BSYNC(BAR_FREE1, NTHR); } else { BSYNC(BAR_FREE0, NTHR); }

        u64 aI[NA], aF[NA], aG[NA], aO[NA];
#pragma unroll
        for (int q = 0; q < NA; q++) { aI[q] = bi0; aF[q] = bf0; aG[q] = bg0; aO[q] = bo0; }

#pragma unroll
        for (int d = 0; d < 5; d++) {
            float4 w = *(const float4*)&wih0[(d * 64 + j) * 4];
            u64 wi = dup2(w.x), wf = dup2(w.y), wg = dup2(w.z), wo = dup2(w.w);
            u64 xv[4];
            load_pairs<NA>(&xc[d * HS + bb], xv);
#pragma unroll
            for (int i = 0; i < NA; i++) {
                fma2(aI[i], xv[i], wi); fma2(aF[i], xv[i], wf);
                fma2(aG[i], xv[i], wg); fma2(aO[i], xv[i], wo);
            }
        }
        gemvK<NA>(whh0, br, j, bb, aI, aF, aG, aO);

        float hn[2 * NA];
        pointwiseN<NA>(aI, aF, aG, aO, c0, hn);
        store_h<NA>(&bw[j * HS + bb], hn);

        if (p) { BARRV(BAR_READY1, NTHR); } else { BARRV(BAR_READY0, NTHR); }

        // stage x[t+1] into the other parity buffer; prefetch x[t+2]
        if (tid < 140) {
            float* xw = p ? xsA : xsB;
            xw[xd * HS + xslot] = xreg;
            int tn = (t + 2 < T_LEN) ? t + 2 : T_LEN - 1;
            xreg = xptr[tn * D_IN];
        }
    }
}

// ===================== LAYER 1 GROUP body =====================
template<int NA>
__device__ __forceinline__ void run_layer1(
    const float* wih1, const float* whh1,
    const float* bufA, const float* bufB, float* h1s,
    const float* __restrict__ b_ih1, const float* __restrict__ b_hh1,
    int j, int bb)
{
    const u64 bi1 = dup2(b_ih1[j]       + b_hh1[j]);
    const u64 bf1 = dup2(b_ih1[64 + j]  + b_hh1[64 + j]);
    const u64 bg1 = dup2(b_ih1[128 + j] + b_hh1[128 + j]);
    const u64 bo1 = dup2(b_ih1[192 + j] + b_hh1[192 + j]);
    float c1[2 * NA];
#pragma unroll
    for (int p = 0; p < 2 * NA; p++) c1[p] = 0.0f;

    // prime the free barriers (both parities available)
    BARRV(BAR_FREE0, NTHR);
    BARRV(BAR_FREE1, NTHR);

    for (int t = 0; t < T_LEN; t++) {
        const int p = t & 1;
        const float* br = p ? bufB : bufA;  // h0[t]

        BSYNC(BAR_L1INT, 256);              // h1 writes of t-1 visible

        u64 aI[NA], aF[NA], aG[NA], aO[NA];
#pragma unroll
        for (int q = 0; q < NA; q++) { aI[q] = bi1; aF[q] = bf1; aG[q] = bg1; aO[q] = bo1; }

        gemvK<NA>(whh1, h1s, j, bb, aI, aF, aG, aO);   // recurrent part (h1[t-1])

        if (p) { BSYNC(BAR_READY1, NTHR); } else { BSYNC(BAR_READY0, NTHR); }

        gemvK<NA>(wih1, br, j, bb, aI, aF, aG, aO);    // input part (h0[t])

        if (p) { BARRV(BAR_FREE1, NTHR); } else { BARRV(BAR_FREE0, NTHR); }

        float hn[2 * NA];
        pointwiseN<NA>(aI, aF, aG, aO, c1, hn);
        // WAR on h1s protected by the ready rendezvous (all L1 passed it
        // after finishing their recurrent reads of h1s)
        store_h<NA>(&h1s[j * HS + bb], hn);
    }
}

__global__ void __launch_bounds__(NTHR, 1)
stocklstm_kernel(const float* __restrict__ x,
                 const float* __restrict__ W_ih0, const float* __restrict__ W_hh0,
                 const float* __restrict__ b_ih0, const float* __restrict__ b_hh0,
                 const float* __restrict__ W_ih1, const float* __restrict__ W_hh1,
                 const float* __restrict__ b_ih1, const float* __restrict__ b_hh1,
                 const float* __restrict__ W1,   const float* __restrict__ b1,
                 const float* __restrict__ W2,   const float* __restrict__ b2,
                 float* __restrict__ out)
{
    extern __shared__ float sm[];
    float* whh0 = sm + OFF_WHH0;
    float* wih1 = sm + OFF_WIH1;
    float* whh1 = sm + OFF_WHH1;
    float* wih0 = sm + OFF_WIH0;
    float* bufA = sm + OFF_B0A;
    float* bufB = sm + OFF_B0B;
    float* h1s  = sm + OFF_H1;
    float* xsA  = sm + OFF_XA;
    float* xsB  = sm + OFF_XB;

    const int tid  = threadIdx.x;
    const int lane = tid & 31;
    const int wg   = (tid >> 5) & 7;              // warp index within layer group
    // NEW MAP: warp = 16 j-values x 2 batch-slots.
    // Lanes 0-15 and 16-31 share the same 16 j's -> weight LDS dedups to 256B (2wf).
    const int j    = (lane & 15) | ((wg & 3) << 4);   // hidden unit 0..63
    const int nh   = wg >> 2;                     // 0: slots {0,1} NA=4; 1: slots {2,3} NA=3
    const int slot = nh * 2 + (lane >> 4);        // slot 0..3
    const int bb   = slot * 8;                    // slot base {0,8,16,24}
    const int B0   = blockIdx.x * NB;

    // ---- stage weights, packed [k][j][4 gates] ----
    for (int idx = tid; idx < 256 * 64; idx += NTHR) {
        int gg = idx >> 6, k = idx & 63;
        int gi = gg >> 6, jj = gg & 63;
        int dst = (k * 64 + jj) * 4 + gi;
        whh0[dst] = W_hh0[idx];
        wih1[dst] = W_ih1[idx];
        whh1[dst] = W_hh1[idx];
    }
    for (int idx = tid; idx < 256 * 5; idx += NTHR) {
        int gg = idx / 5, d = idx - 5 * gg;
        wih0[(d * 64 + (gg & 63)) * 4 + (gg >> 6)] = W_ih0[idx];
    }
    for (int idx = tid; idx < 64 * HS; idx += NTHR) {
        bufA[idx] = 0.0f; bufB[idx] = 0.0f; h1s[idx] = 0.0f;
    }
    __syncthreads();   // weights + zeroed state visible to all

    if (tid < 256) {
        if (nh == 0) run_layer0<4>(wih0, whh0, bufA, bufB, xsA, xsB, x, b_ih0, b_hh0, j, bb, B0, tid);
        else         run_layer0<3>(wih0, whh0, bufA, bufB, xsA, xsB, x, b_ih0, b_hh0, j, bb, B0, tid);
    } else {
        if (nh == 0) run_layer1<4>(wih1, whh1, bufA, bufB, h1s, b_ih1, b_hh1, j, bb);
        else         run_layer1<3>(wih1, whh1, bufA, bufB, h1s, b_ih1, b_hh1, j, bb);
    }
    __syncthreads();

    // ================= MLP head: out = W2 @ relu(W1 @ h2 + b1) + b2 =========
    if (tid < NB && B0 + tid < B_TOT) {
        const int slt = tid + (tid >= 22 ? 2 : 0);
        float acc = b2[0];
#pragma unroll 1
        for (int u = 0; u < 32; u++) {
            float s = b1[u];
            const float* wr = W1 + u * 64;
#pragma unroll
            for (int k = 0; k < 64; k++) s += wr[k] * h1s[k * HS + slt];
            acc += W2[u] * fmaxf(s, 0.0f);
        }
        out[B0 + tid] = acc;
    }
}

extern "C" void kernel_launch(void* const* d_in, const int* in_sizes, int n_in,
                              void* d_out, int out_size)
{
    const float* x    = (const float*)d_in[0];
    const float* Wih0 = (const float*)d_in[1];
    const float* Whh0 = (const float*)d_in[2];
    const float* bih0 = (const float*)d_in[3];
    const float* bhh0 = (const float*)d_in[4];
    const float* Wih1 = (const float*)d_in[5];
    const float* Whh1 = (const float*)d_in[6];
    const float* bih1 = (const float*)d_in[7];
    const float* bhh1 = (const float*)d_in[8];
    const float* W1   = (const float*)d_in[9];
    const float* b1   = (const float*)d_in[10];
    const float* W2   = (const float*)d_in[11];
    const float* b2   = (const float*)d_in[12];
    float* out = (float*)d_out;

    cudaFuncSetAttribute(stocklstm_kernel,
                         cudaFuncAttributeMaxDynamicSharedMemorySize, SMEM_BYTES);
    stocklstm_kernel<<<GRID, NTHR, SMEM_BYTES>>>(
        x, Wih0, Whh0, bih0, bhh0, Wih1, Whh1, bih1, bhh1, W1, b1, W2, b2, out);
}

// round 12
// speedup vs baseline: 1.0011x; 1.0011x over previous
#include <cuda_runtime.h>

#define B_TOT 4096
#define T_LEN 512
#define D_IN  5
#define NB    28          // batches per CTA (slot space 32: 8+8+6+6; slots 22,23,30,31 unused)
#define GRID  147         // ceil(4096/28), single wave
#define NTHR  512         // warps 0-7: layer0, warps 8-15: layer1
#define HS    36          // padded row stride (floats) for h/x state

// shared memory layout (float offsets) — identical to R10
#define OFF_WHH0 0
#define OFF_WIH1 16384
#define OFF_WHH1 32768
#define OFF_WIH0 49152                 // 5*64*4 = 1280
#define OFF_B0A  (49152 + 1280)        // h0 buffer 0: 64*36 = 2304
#define OFF_B0B  (OFF_B0A + 2304)      // h0 buffer 1
#define OFF_H1   (OFF_B0B + 2304)
#define OFF_XA   (OFF_H1 + 2304)       // 5*36 = 180
#define OFF_XB   (OFF_XA + 180)
#define SMEM_FLOATS (OFF_XB + 180)     // 57,704 floats
#define SMEM_BYTES  (SMEM_FLOATS * 4)  // 230,816 B (boot-proven)

// named barriers (R9/R10-proven protocol)
#define BAR_READY0 1
#define BAR_READY1 2
#define BAR_FREE0  3
#define BAR_FREE1  4
#define BAR_L1INT  7

#define BSYNC(id, cnt) asm volatile("bar.sync %0, %1;" :: "n"(id), "n"(cnt) : "memory")
#define BARRV(id, cnt) asm volatile("bar.arrive %0, %1;" :: "n"(id), "n"(cnt) : "memory")

typedef unsigned long long u64;

union F2U { float2 f; u64 u; };

__device__ __forceinline__ u64 dup2(float x) {
    F2U t; t.f = make_float2(x, x); return t.u;
}
__device__ __forceinline__ float2 unpk(u64 v) { F2U t; t.u = v; return t.f; }

__device__ __forceinline__ void fma2(u64& a, u64 x, u64 w) {
    asm("fma.rn.f32x2 %0, %1, %2, %0;" : "+l"(a) : "l"(x), "l"(w));
}

// MUFU.TANH (validated: rel_err ~7e-7)
__device__ __forceinline__ float tanha(float x) {
    float y; asm("tanh.approx.f32 %0, %1;" : "=f"(y) : "f"(x)); return y;
}
__device__ __forceinline__ float sigf(float x) {
    return fmaf(0.5f, tanha(0.5f * x), 0.5f);
}

// load NA u64 batch-pairs from state row (16B-aligned base; NA=3 tail is 8B-aligned)
template<int NA>
__device__ __forceinline__ void load_pairs(const float* base, u64* hv) {
    ulonglong2 a = *(const ulonglong2*)base;
    hv[0] = a.x; hv[1] = a.y;
    if (NA == 4) {
        ulonglong2 b = *(const ulonglong2*)(base + 4);
        hv[2] = b.x; hv[3] = b.y;
    } else {
        hv[2] = *(const u64*)(base + 4);
    }
}

template<int NA>
__device__ __forceinline__ void store_h(float* dst, const float* hn) {
    *(float4*)dst = make_float4(hn[0], hn[1], hn[2], hn[3]);
    if (NA == 4) *(float4*)(dst + 4) = make_float4(hn[4], hn[5], hn[6], hn[7]);
    else         *(float2*)(dst + 4) = make_float2(hn[4], hn[5]);
}

// one 64-k gate GEMV accumulation pass
template<int NA>
__device__ __forceinline__ void gemvK(const float* __restrict__ W,
                                      const float* __restrict__ hsrc,
                                      int j, int bb,
                                      u64* aI, u64* aF, u64* aG, u64* aO)
{
#pragma unroll 4
    for (int k = 0; k < 64; k++) {
        float4 w = *(const float4*)&W[(k * 64 + j) * 4];
        u64 wi = dup2(w.x), wf = dup2(w.y), wg = dup2(w.z), wo = dup2(w.w);
        u64 hv[4];
        load_pairs<NA>(&hsrc[k * HS + bb], hv);
#pragma unroll
        for (int i = 0; i < NA; i++) {
            fma2(aI[i], hv[i], wi); fma2(aF[i], hv[i], wf);
            fma2(aG[i], hv[i], wg); fma2(aO[i], hv[i], wo);
        }
    }
}

template<int NA>
__device__ __forceinline__ void pointwiseN(const u64* aI, const u64* aF,
                                           const u64* aG, const u64* aO,
                                           float* c, float* hn)
{
#pragma unroll
    for (int p = 0; p < NA; p++) {
        float2 vi = unpk(aI[p]), vf = unpk(aF[p]), vg = unpk(aG[p]), vo = unpk(aO[p]);
        float ca = sigf(vf.x) * c[2 * p]     + sigf(vi.x) * tanha(vg.x);
        float cb = sigf(vf.y) * c[2 * p + 1] + sigf(vi.y) * tanha(vg.y);
        c[2 * p] = ca; c[2 * p + 1] = cb;
        hn[2 * p]     = sigf(vo.x) * tanha(ca);
        hn[2 * p + 1] = sigf(vo.y) * tanha(cb);
    }
}

// ===================== LAYER 0 GROUP body =====================
template<int NA>
__device__ __forceinline__ void run_layer0(
    const float* wih0, const float* whh0,
    float* bufA, float* bufB, float* xsA, float* xsB,
    const float* __restrict__ x,
    const float* __restrict__ b_ih0, const float* __restrict__ b_hh0,
    int j, int bb, int B0, int tid)
{
    const u64 bi0 = dup2(b_ih0[j]       + b_hh0[j]);
    const u64 bf0 = dup2(b_ih0[64 + j]  + b_hh0[64 + j]);
    const u64 bg0 = dup2(b_ih0[128 + j] + b_hh0[128 + j]);
    const u64 bo0 = dup2(b_ih0[192 + j] + b_hh0[192 + j]);
    float c0[2 * NA];
#pragma unroll
    for (int p = 0; p < 2 * NA; p++) c0[p] = 0.0f;

    // x staging: threads 0..139 own (local batch l, feature xd); slot map skips 22,23
    const int l  = tid / 5;
    const int xd = tid - l * 5;
    int gb = B0 + l; if (gb > B_TOT - 1) gb = B_TOT - 1;   // edge-CTA clamp
    const int xslot = l + (l >= 22 ? 2 : 0);
    const float* xptr = x + (size_t)gb * (T_LEN * D_IN) + xd;
    float xreg = 0.0f;
    if (tid < 140) {
        xsA[xd * HS + xslot] = xptr[0];   // stage x[0]
        xreg = xptr[D_IN];                // prefetch x[1]
    }

    for (int t = 0; t < T_LEN; t++) {
        const int p = t & 1;
        float* bw = p ? bufB : bufA;        // write h0[t]
        const float* br = p ? bufA : bufB;  // read h0[t-1]
        const float* xc = p ? xsB : xsA;

        if (p) { BSYNC(BAR_FREE1, NTHR); } else { BSYNC(BAR_FREE0, NTHR); }

        u64 aI[NA], aF[NA], aG[NA], aO[NA];
#pragma unroll
        for (int q = 0; q < NA; q++) { aI[q] = bi0; aF[q] = bf0; aG[q] = bg0; aO[q] = bo0; }

#pragma unroll
        for (int d = 0; d < 5; d++) {
            float4 w = *(const float4*)&wih0[(d * 64 + j) * 4];
            u64 wi = dup2(w.x), wf = dup2(w.y), wg = dup2(w.z), wo = dup2(w.w);
            u64 xv[4];
            load_pairs<NA>(&xc[d * HS + bb], xv);
#pragma unroll
            for (int i = 0; i < NA; i++) {
                fma2(aI[i], xv[i], wi); fma2(aF[i], xv[i], wf);
                fma2(aG[i], xv[i], wg); fma2(aO[i], xv[i], wo);
            }
        }
        gemvK<NA>(whh0, br, j, bb, aI, aF, aG, aO);

        float hn[2 * NA];
        pointwiseN<NA>(aI, aF, aG, aO, c0, hn);
        store_h<NA>(&bw[j * HS + bb], hn);

        if (p) { BARRV(BAR_READY1, NTHR); } else { BARRV(BAR_READY0, NTHR); }

        // stage x[t+1] into the other parity buffer; prefetch x[t+2]
        if (tid < 140) {
            float* xw = p ? xsA : xsB;
            xw[xd * HS + xslot] = xreg;
            int tn = (t + 2 < T_LEN) ? t + 2 : T_LEN - 1;
            xreg = xptr[tn * D_IN];
        }
    }
}

// ===================== LAYER 1 GROUP body =====================
template<int NA>
__device__ __forceinline__ void run_layer1(
    const float* wih1, const float* whh1,
    const float* bufA, const float* bufB, float* h1s,
    const float* __restrict__ b_ih1, const float* __restrict__ b_hh1,
    int j, int bb)
{
    const u64 bi1 = dup2(b_ih1[j]       + b_hh1[j]);
    const u64 bf1 = dup2(b_ih1[64 + j]  + b_hh1[64 + j]);
    const u64 bg1 = dup2(b_ih1[128 + j] + b_hh1[128 + j]);
    const u64 bo1 = dup2(b_ih1[192 + j] + b_hh1[192 + j]);
    float c1[2 * NA];
#pragma unroll
    for (int p = 0; p < 2 * NA; p++) c1[p] = 0.0f;

    // prime the free barriers (both parities available)
    BARRV(BAR_FREE0, NTHR);
    BARRV(BAR_FREE1, NTHR);

    for (int t = 0; t < T_LEN; t++) {
        const int p = t & 1;
        const float* br = p ? bufB : bufA;  // h0[t]

        BSYNC(BAR_L1INT, 256);              // h1 writes of t-1 visible

        u64 aI[NA], aF[NA], aG[NA], aO[NA];
#pragma unroll
        for (int q = 0; q < NA; q++) { aI[q] = bi1; aF[q] = bf1; aG[q] = bg1; aO[q] = bo1; }

        gemvK<NA>(whh1, h1s, j, bb, aI, aF, aG, aO);   // recurrent part (h1[t-1])

        if (p) { BSYNC(BAR_READY1, NTHR); } else { BSYNC(BAR_READY0, NTHR); }

        gemvK<NA>(wih1, br, j, bb, aI, aF, aG, aO);    // input part (h0[t])

        if (p) { BARRV(BAR_FREE1, NTHR); } else { BARRV(BAR_FREE0, NTHR); }

        float hn[2 * NA];
        pointwiseN<NA>(aI, aF, aG, aO, c1, hn);
        // WAR on h1s protected by the ready rendezvous (all L1 passed it
        // after finishing their recurrent reads of h1s)
        store_h<NA>(&h1s[j * HS + bb], hn);
    }
}

__global__ void __launch_bounds__(NTHR, 1)
stocklstm_kernel(const float* __restrict__ x,
                 const float* __restrict__ W_ih0, const float* __restrict__ W_hh0,
                 const float* __restrict__ b_ih0, const float* __restrict__ b_hh0,
                 const float* __restrict__ W_ih1, const float* __restrict__ W_hh1,
                 const float* __restrict__ b_ih1, const float* __restrict__ b_hh1,
                 const float* __restrict__ W1,   const float* __restrict__ b1,
                 const float* __restrict__ W2,   const float* __restrict__ b2,
                 float* __restrict__ out)
{
    extern __shared__ float sm[];
    float* whh0 = sm + OFF_WHH0;
    float* wih1 = sm + OFF_WIH1;
    float* whh1 = sm + OFF_WHH1;
    float* wih0 = sm + OFF_WIH0;
    float* bufA = sm + OFF_B0A;
    float* bufB = sm + OFF_B0B;
    float* h1s  = sm + OFF_H1;
    float* xsA  = sm + OFF_XA;
    float* xsB  = sm + OFF_XB;

    const int tid  = threadIdx.x;
    const int lane = tid & 31;
    const int wg   = (tid >> 5) & 7;              // warp index within layer group
    // NEW MAP: warp = 16 j-values x 2 batch-slots.
    // Lanes 0-15 and 16-31 share the same 16 j's -> weight LDS dedups to 256B (2wf).
    const int j    = (lane & 15) | ((wg & 3) << 4);   // hidden unit 0..63
    const int nh   = wg >> 2;                     // 0: slots {0,1} NA=4; 1: slots {2,3} NA=3
    const int slot = nh * 2 + (lane >> 4);        // slot 0..3
    const int bb   = slot * 8;                    // slot base {0,8,16,24}
    const int B0   = blockIdx.x * NB;

    // ---- stage weights, packed [k][j][4 gates] ----
    for (int idx = tid; idx < 256 * 64; idx += NTHR) {
        int gg = idx >> 6, k = idx & 63;
        int gi = gg >> 6, jj = gg & 63;
        int dst = (k * 64 + jj) * 4 + gi;
        whh0[dst] = W_hh0[idx];
        wih1[dst] = W_ih1[idx];
        whh1[dst] = W_hh1[idx];
    }
    for (int idx = tid; idx < 256 * 5; idx += NTHR) {
        int gg = idx / 5, d = idx - 5 * gg;
        wih0[(d * 64 + (gg & 63)) * 4 + (gg >> 6)] = W_ih0[idx];
    }
    for (int idx = tid; idx < 64 * HS; idx += NTHR) {
        bufA[idx] = 0.0f; bufB[idx] = 0.0f; h1s[idx] = 0.0f;
    }
    __syncthreads();   // weights + zeroed state visible to all

    if (tid < 256) {
        if (nh == 0) run_layer0<4>(wih0, whh0, bufA, bufB, xsA, xsB, x, b_ih0, b_hh0, j, bb, B0, tid);
        else         run_layer0<3>(wih0, whh0, bufA, bufB, xsA, xsB, x, b_ih0, b_hh0, j, bb, B0, tid);
    } else {
        if (nh == 0) run_layer1<4>(wih1, whh1, bufA, bufB, h1s, b_ih1, b_hh1, j, bb);
        else         run_layer1<3>(wih1, whh1, bufA, bufB, h1s, b_ih1, b_hh1, j, bb);
    }
    __syncthreads();

    // ================= MLP head: out = W2 @ relu(W1 @ h2 + b1) + b2 =========
    if (tid < NB && B0 + tid < B_TOT) {
        const int slt = tid + (tid >= 22 ? 2 : 0);
        float acc = b2[0];
#pragma unroll 1
        for (int u = 0; u < 32; u++) {
            float s = b1[u];
            const float* wr = W1 + u * 64;
#pragma unroll
            for (int k = 0; k < 64; k++) s += wr[k] * h1s[k * HS + slt];
            acc += W2[u] * fmaxf(s, 0.0f);
        }
        out[B0 + tid] = acc;
    }
}

extern "C" void kernel_launch(void* const* d_in, const int* in_sizes, int n_in,
                              void* d_out, int out_size)
{
    const float* x    = (const float*)d_in[0];
    const float* Wih0 = (const float*)d_in[1];
    const float* Whh0 = (const float*)d_in[2];
    const float* bih0 = (const float*)d_in[3];
    const float* bhh0 = (const float*)d_in[4];
    const float* Wih1 = (const float*)d_in[5];
    const float* Whh1 = (const float*)d_in[6];
    const float* bih1 = (const float*)d_in[7];
    const float* bhh1 = (const float*)d_in[8];
    const float* W1   = (const float*)d_in[9];
    const float* b1   = (const float*)d_in[10];
    const float* W2   = (const float*)d_in[11];
    const float* b2   = (const float*)d_in[12];
    float* out = (float*)d_out;

    cudaFuncSetAttribute(stocklstm_kernel,
                         cudaFuncAttributeMaxDynamicSharedMemorySize, SMEM_BYTES);
    stocklstm_kernel<<<GRID, NTHR, SMEM_BYTES>>>(
        x, Wih0, Whh0, bih0, bhh0, Wih1, Whh1, bih1, bhh1, W1, b1, W2, b2, out);
}

// round 14
// speedup vs baseline: 1.8754x; 1.8733x over previous
#include <cuda_runtime.h>
#include <cuda_bf16.h>

typedef unsigned int u32;
typedef unsigned short u16;

#define T_LEN 512
#define D_IN  5
#define NB    32
#define GRID  128
#define NTHR  256          // 8 warps; warp w owns M-tiles {2w, 2w+1}

// ---- smem byte offsets ----
#define OFF_A0  0          // L0 A frags: 16 tiles x 2 splits x 4 kb x 512B = 65536
#define OFF_A1  65536      // L1 A frags: 16 x 2 x 8 x 512B = 131072
#define OFF_B0H 196608     // h0 hi  [32][72] bf16 = 4608
#define OFF_B0L 201216     // h0 lo
#define OFF_B1H 205824     // [h1|h0] hi [32][136] bf16 = 8704
#define OFF_B1L 214528     // [h1|h0] lo
#define OFF_XS  223232     // x stage [5][32] f32 = 640
#define SMEM_BYTES 223872

#define PK0 72             // B0 pitch (bf16 elems): 144B -> conflict-free b-frag loads
#define PK1 136            // B1 pitch: 272B

__device__ __forceinline__ u16 bfbits(float v) {
    __nv_bfloat16 b = __float2bfloat16(v);
    return reinterpret_cast<__nv_bfloat16_raw&>(b).x;
}
__device__ __forceinline__ float bff(u16 b) {
    __nv_bfloat16_raw r; r.x = b;
    return __bfloat162float(*reinterpret_cast<__nv_bfloat16*>(&r));
}
// pack two adjacent weights as bf16 pair; s=0 -> hi split, s=1 -> lo split
__device__ __forceinline__ u32 pack_split(float v0, float v1, int s) {
    u16 h0 = bfbits(v0), h1 = bfbits(v1);
    if (s) { h0 = bfbits(v0 - bff(h0)); h1 = bfbits(v1 - bff(h1)); }
    return (u32)h0 | ((u32)h1 << 16);
}

__device__ __forceinline__ u32 smem_u32(const void* p) {
    u32 a;
    asm("{ .reg .u64 t; cvta.to.shared.u64 t, %1; cvt.u32.u64 %0, t; }" : "=r"(a) : "l"(p));
    return a;
}
__device__ __forceinline__ void lds128(u32* v, u32 addr) {
    asm volatile("ld.shared.v4.u32 {%0,%1,%2,%3}, [%4];"
        : "=r"(v[0]), "=r"(v[1]), "=r"(v[2]), "=r"(v[3]) : "r"(addr));
}
__device__ __forceinline__ void mma16816(float* d, const u32* a, u32 b0, u32 b1) {
    asm volatile("mma.sync.aligned.m16n8k16.row.col.f32.bf16.bf16.f32 "
        "{%0,%1,%2,%3}, {%4,%5,%6,%7}, {%8,%9}, {%0,%1,%2,%3};"
        : "+f"(d[0]), "+f"(d[1]), "+f"(d[2]), "+f"(d[3])
        : "r"(a[0]), "r"(a[1]), "r"(a[2]), "r"(a[3]), "r"(b0), "r"(b1));
}

// MUFU.TANH (validated rel_err impact ~0 in scalar rounds)
__device__ __forceinline__ float tanha(float x) {
    float y; asm("tanh.approx.f32 %0, %1;" : "=f"(y) : "f"(x)); return y;
}
__device__ __forceinline__ float sigf(float x) {
    return fmaf(0.5f, tanha(0.5f * x), 0.5f);
}

// A-frag byte offsets (frag-contiguous: [tile][split][kb][lane][4xu32])
__device__ __forceinline__ u32 a0_off(int tile, int s, int kb, int lane) {
    return OFF_A0 + (u32)((((tile * 2 + s) * 4 + kb) * 32 + lane) * 16);
}
__device__ __forceinline__ u32 a1_off(int tile, int s, int kb, int lane) {
    return OFF_A1 + (u32)((((tile * 2 + s) * 8 + kb) * 32 + lane) * 16);
}

__global__ void __launch_bounds__(NTHR, 1)
stocklstm_mma_kernel(const float* __restrict__ x,
                     const float* __restrict__ W_ih0, const float* __restrict__ W_hh0,
                     const float* __restrict__ b_ih0, const float* __restrict__ b_hh0,
                     const float* __restrict__ W_ih1, const float* __restrict__ W_hh1,
                     const float* __restrict__ b_ih1, const float* __restrict__ b_hh1,
                     const float* __restrict__ W1,   const float* __restrict__ b1,
                     const float* __restrict__ W2,   const float* __restrict__ b2,
                     float* __restrict__ out)
{
    extern __shared__ char sm[];
    const u32 sb = smem_u32(sm);
    const int tid  = threadIdx.x;
    const int w    = tid >> 5;
    const int lane = tid & 31;
    const int grp  = lane >> 2;      // 0..7
    const int tig  = lane & 3;       // 0..3
    const int par  = grp >> 2;       // 0: lane holds (i,g); 1: (f,o)
    const int B0   = blockIdx.x * NB;

    // ---- stage A0 frags (Whh0, gate-interleaved rows: row = gate*4 + ulocal) ----
    for (int idx = tid; idx < 16384; idx += NTHR) {
        int reg = idx & 3, ln = (idx >> 2) & 31, kb = (idx >> 7) & 3;
        int s = (idx >> 9) & 1, tile = idx >> 10;
        int g2 = ln >> 2, t2 = ln & 3;
        int row = g2 + (reg & 1) * 8;                 // 0..15 within tile
        int col = kb * 16 + t2 * 2 + (reg >> 1) * 8;  // 0..63
        int grow = ((row >> 2) << 6) + tile * 4 + (row & 3);  // gate*64 + unit
        ((u32*)(sm + OFF_A0))[idx] =
            pack_split(W_hh0[grow * 64 + col], W_hh0[grow * 64 + col + 1], s);
    }
    // ---- stage A1 frags ([Whh1 | Wih1] along K=128) ----
    for (int idx = tid; idx < 32768; idx += NTHR) {
        int reg = idx & 3, ln = (idx >> 2) & 31, kb = (idx >> 7) & 7;
        int s = (idx >> 10) & 1, tile = idx >> 11;
        int g2 = ln >> 2, t2 = ln & 3;
        int row = g2 + (reg & 1) * 8;
        int col = kb * 16 + t2 * 2 + (reg >> 1) * 8;  // 0..127
        int grow = ((row >> 2) << 6) + tile * 4 + (row & 3);
        float v0, v1;
        if (col < 64) { v0 = W_hh1[grow * 64 + col];      v1 = W_hh1[grow * 64 + col + 1]; }
        else          { v0 = W_ih1[grow * 64 + col - 64]; v1 = W_ih1[grow * 64 + col - 63]; }
        ((u32*)(sm + OFF_A1))[idx] = pack_split(v0, v1, s);
    }
    // ---- zero B buffers (h0 = h1 = 0), contiguous 26624B ----
    for (int idx = tid; idx < 6656; idx += NTHR)
        ((u32*)(sm + OFF_B0H))[idx] = 0u;

    // ---- per-thread constants ----
    const int tg[2] = { 2 * w, 2 * w + 1 };
    const int ga = grp >> 2;          // gate_a: 0(i) or 1(f)
    const int gc = ga + 2;            // gate_c: 2(g) or 3(o)
    const int uu[2] = { 4 * tg[0] + (grp & 3), 4 * tg[1] + (grp & 3) };

    float bA0[2], bC0[2], bA1[2], bC1[2];
    float wxA[2][5], wxC[2][5];
#pragma unroll
    for (int t2 = 0; t2 < 2; t2++) {
        int ra = ga * 64 + uu[t2], rc = gc * 64 + uu[t2];
        bA0[t2] = b_ih0[ra] + b_hh0[ra];
        bC0[t2] = b_ih0[rc] + b_hh0[rc];
        bA1[t2] = b_ih1[ra] + b_hh1[ra];
        bC1[t2] = b_ih1[rc] + b_hh1[rc];
#pragma unroll
        for (int d = 0; d < 5; d++) {
            wxA[t2][d] = W_ih0[ra * 5 + d];
            wxC[t2][d] = W_ih0[rc * 5 + d];
        }
    }

    float c0[8], c1[8], hfin[8];
#pragma unroll
    for (int p = 0; p < 8; p++) { c0[p] = 0.0f; c1[p] = 0.0f; hfin[p] = 0.0f; }

    // ---- x staging: threads 0..159 own (batch xl, feature xd) ----
    const int xl = tid / 5, xd = tid - xl * 5;
    const float* xptr = x + (size_t)(B0 + xl) * (T_LEN * D_IN) + xd;
    float xreg = 0.0f;
    if (tid < 160) {
        ((float*)(sm + OFF_XS))[xd * 32 + xl] = xptr[0];
        xreg = xptr[D_IN];
    }
    __syncthreads();

#pragma unroll 1
    for (int t = 0; t < T_LEN; t++) {
        float d[2][4][4];
        // ===== L0 D-init: bias + Wih0 @ x =====
#pragma unroll
        for (int t2 = 0; t2 < 2; t2++)
#pragma unroll
            for (int nb = 0; nb < 4; nb++) {
                float s0 = bA0[t2], s1 = bA0[t2], s2 = bC0[t2], s3 = bC0[t2];
#pragma unroll
                for (int dd = 0; dd < 5; dd++) {
                    float2 xv = *(const float2*)((const float*)(sm + OFF_XS) + dd * 32 + nb * 8 + tig * 2);
                    s0 = fmaf(wxA[t2][dd], xv.x, s0); s1 = fmaf(wxA[t2][dd], xv.y, s1);
                    s2 = fmaf(wxC[t2][dd], xv.x, s2); s3 = fmaf(wxC[t2][dd], xv.y, s3);
                }
                d[t2][nb][0] = s0; d[t2][nb][1] = s1; d[t2][nb][2] = s2; d[t2][nb][3] = s3;
            }
        // ===== L0 mma: Whh0_split @ h0_split =====
#pragma unroll
        for (int kb = 0; kb < 4; kb++) {
            u32 ah[2][4], al[2][4];
            lds128(ah[0], sb + a0_off(tg[0], 0, kb, lane));
            lds128(al[0], sb + a0_off(tg[0], 1, kb, lane));
            lds128(ah[1], sb + a0_off(tg[1], 0, kb, lane));
            lds128(al[1], sb + a0_off(tg[1], 1, kb, lane));
#pragma unroll
            for (int nb = 0; nb < 4; nb++) {
                u32 bo = (u32)((nb * 8 + grp) * (PK0 * 2) + (kb * 16 + tig * 2) * 2);
                u32 bh0 = *(const u32*)(sm + OFF_B0H + bo);
                u32 bh1 = *(const u32*)(sm + OFF_B0H + bo + 16);
                u32 bl0 = *(const u32*)(sm + OFF_B0L + bo);
                u32 bl1 = *(const u32*)(sm + OFF_B0L + bo + 16);
#pragma unroll
                for (int t2 = 0; t2 < 2; t2++) {
                    mma16816(d[t2][nb], ah[t2], bh0, bh1);
                    mma16816(d[t2][nb], ah[t2], bl0, bl1);
                    mma16816(d[t2][nb], al[t2], bh0, bh1);
                }
            }
        }
        __syncthreads();   // S1: all L0 B-reads (h0 old) + x reads done

        // stage x[t+1]; prefetch x[t+2]
        if (tid < 160) {
            ((float*)(sm + OFF_XS))[xd * 32 + xl] = xreg;
            int tn = (t + 2 < T_LEN) ? t + 2 : T_LEN - 1;
            xreg = xptr[tn * D_IN];
        }

        // ===== pointwise L0 (warp-local via shfl) =====
#pragma unroll
        for (int t2 = 0; t2 < 2; t2++)
#pragma unroll
            for (int nb = 0; nb < 4; nb++) {
                float d0 = d[t2][nb][0], d1 = d[t2][nb][1], d2 = d[t2][nb][2], d3 = d[t2][nb][3];
                float p0 = __shfl_xor_sync(0xFFFFFFFFu, d0, 16);
                float p1 = __shfl_xor_sync(0xFFFFFFFFu, d1, 16);
                float p2 = __shfl_xor_sync(0xFFFFFFFFu, d2, 16);
                float p3 = __shfl_xor_sync(0xFFFFFFFFu, d3, 16);
                float vi = par ? p1 : d0;
                float vf = par ? d1 : p0;
                float vg = par ? p3 : d2;
                float vo = par ? d3 : p2;
                float cc = sigf(vf) * c0[t2 * 4 + nb] + sigf(vi) * tanha(vg);
                c0[t2 * 4 + nb] = cc;
                float h = sigf(vo) * tanha(cc);
                u16 hb = bfbits(h);
                u16 lb = bfbits(h - bff(hb));
                int b = nb * 8 + tig * 2 + par;
                int u = uu[t2];
                ((u16*)(sm + OFF_B0H))[b * PK0 + u] = hb;        // next step's L0
                ((u16*)(sm + OFF_B0L))[b * PK0 + u] = lb;
                ((u16*)(sm + OFF_B1H))[b * PK1 + 64 + u] = hb;   // this step's L1 (Wih1 half)
                ((u16*)(sm + OFF_B1L))[b * PK1 + 64 + u] = lb;
            }
        __syncthreads();   // S2: h0 new visible

        // ===== L1 D-init (bias) + mma: [Whh1|Wih1]_split @ [h1;h0]_split =====
#pragma unroll
        for (int t2 = 0; t2 < 2; t2++)
#pragma unroll
            for (int nb = 0; nb < 4; nb++) {
                d[t2][nb][0] = bA1[t2]; d[t2][nb][1] = bA1[t2];
                d[t2][nb][2] = bC1[t2]; d[t2][nb][3] = bC1[t2];
            }
#pragma unroll
        for (int kb = 0; kb < 8; kb++) {
            u32 ah[2][4], al[2][4];
            lds128(ah[0], sb + a1_off(tg[0], 0, kb, lane));
            lds128(al[0], sb + a1_off(tg[0], 1, kb, lane));
            lds128(ah[1], sb + a1_off(tg[1], 0, kb, lane));
            lds128(al[1], sb + a1_off(tg[1], 1, kb, lane));
#pragma unroll
            for (int nb = 0; nb < 4; nb++) {
                u32 bo = (u32)((nb * 8 + grp) * (PK1 * 2) + (kb * 16 + tig * 2) * 2);
                u32 bh0 = *(const u32*)(sm + OFF_B1H + bo);
                u32 bh1 = *(const u32*)(sm + OFF_B1H + bo + 16);
                u32 bl0 = *(const u32*)(sm + OFF_B1L + bo);
                u32 bl1 = *(const u32*)(sm + OFF_B1L + bo + 16);
#pragma unroll
                for (int t2 = 0; t2 < 2; t2++) {
                    mma16816(d[t2][nb], ah[t2], bh0, bh1);
                    mma16816(d[t2][nb], ah[t2], bl0, bl1);
                    mma16816(d[t2][nb], al[t2], bh0, bh1);
                }
            }
        }
        __syncthreads();   // S3: all L1 B-reads done (h1 WAR safe)

        // ===== pointwise L1 =====
#pragma unroll
        for (int t2 = 0; t2 < 2; t2++)
#pragma unroll
            for (int nb = 0; nb < 4; nb++) {
                float d0 = d[t2][nb][0], d1 = d[t2][nb][1], d2 = d[t2][nb][2], d3 = d[t2][nb][3];
                float p0 = __shfl_xor_sync(0xFFFFFFFFu, d0, 16);
                float p1 = __shfl_xor_sync(0xFFFFFFFFu, d1, 16);
                float p2 = __shfl_xor_sync(0xFFFFFFFFu, d2, 16);
                float p3 = __shfl_xor_sync(0xFFFFFFFFu, d3, 16);
                float vi = par ? p1 : d0;
                float vf = par ? d1 : p0;
                float vg = par ? p3 : d2;
                float vo = par ? d3 : p2;
                float cc = sigf(vf) * c1[t2 * 4 + nb] + sigf(vi) * tanha(vg);
                c1[t2 * 4 + nb] = cc;
                float h = sigf(vo) * tanha(cc);
                hfin[t2 * 4 + nb] = h;
                u16 hb = bfbits(h);
                u16 lb = bfbits(h - bff(hb));
                int b = nb * 8 + tig * 2 + par;
                int u = uu[t2];
                ((u16*)(sm + OFF_B1H))[b * PK1 + u] = hb;   // h1 (Whh1 half)
                ((u16*)(sm + OFF_B1L))[b * PK1 + u] = lb;
            }
        // h1-new visibility for next step's L1 covered by next iter's S2
    }

    // ---- stash final h1 (fp32) for the MLP head (reuse B0 region) ----
    {
        float* scr = (float*)(sm + OFF_B0H);   // [64][33] f32 = 8448B <= 9216
#pragma unroll
        for (int t2 = 0; t2 < 2; t2++)
#pragma unroll
            for (int nb = 0; nb < 4; nb++) {
                int b = nb * 8 + tig * 2 + par;
                scr[uu[t2] * 33 + b] = hfin[t2 * 4 + nb];
            }
    }
    __syncthreads();

    // ---- MLP head: out = W2 @ relu(W1 @ h2 + b1) + b2 ----
    if (tid < NB) {
        const float* scr = (const float*)(sm + OFF_B0H);
        float acc = b2[0];
#pragma unroll 1
        for (int u = 0; u < 32; u++) {
            float s = b1[u];
            const float* wr = W1 + u * 64;
#pragma unroll
            for (int k = 0; k < 64; k++) s += wr[k] * scr[k * 33 + tid];
            acc += W2[u] * fmaxf(s, 0.0f);
        }
        out[B0 + tid] = acc;
    }
}

extern "C" void kernel_launch(void* const* d_in, const int* in_sizes, int n_in,
                              void* d_out, int out_size)
{
    const float* x    = (const float*)d_in[0];
    const float* Wih0 = (const float*)d_in[1];
    const float* Whh0 = (const float*)d_in[2];
    const float* bih0 = (const float*)d_in[3];
    const float* bhh0 = (const float*)d_in[4];
    const float* Wih1 = (const float*)d_in[5];
    const float* Whh1 = (const float*)d_in[6];
    const float* bih1 = (const float*)d_in[7];
    const float* bhh1 = (const float*)d_in[8];
    const float* W1   = (const float*)d_in[9];
    const float* b1   = (const float*)d_in[10];
    const float* W2   = (const float*)d_in[11];
    const float* b2   = (const float*)d_in[12];
    float* out = (float*)d_out;

    cudaFuncSetAttribute(stocklstm_mma_kernel,
                         cudaFuncAttributeMaxDynamicSharedMemorySize, SMEM_BYTES);
    stocklstm_mma_kernel<<<GRID, NTHR, SMEM_BYTES>>>(
        x, Wih0, Whh0, bih0, bhh0, Wih1, Whh1, bih1, bhh1, W1, b1, W2, b2, out);
}

// round 15
// speedup vs baseline: 2.4744x; 1.3194x over previous
#include <cuda_runtime.h>
#include <cuda_fp16.h>

typedef unsigned int u32;
typedef unsigned short u16;

#define T_LEN 512
#define D_IN  5
#define NB    32
#define GRID  128
#define NTHR  256          // 8 warps; warp w owns M-tiles {2w, 2w+1}

// ---- smem byte offsets ----
#define OFF_A0  0          // L0 A frags (fp16): 16 tiles x 4 kb x 512B = 32768
#define OFF_A1  32768      // L1 A frags: 16 x 8 x 512B = 65536
#define OFF_B0H 98304      // h0 hi  [32][72] fp16 = 4608
#define OFF_B0L 102912     // h0 lo
#define OFF_B1H 107520     // [h1|h0] hi [32][136] fp16 = 8704
#define OFF_B1L 116224     // [h1|h0] lo
#define OFF_XS  124928     // x stage [5][32] f32 = 640
#define SMEM_BYTES 125568

#define PK0 72             // B0 pitch (fp16 elems): 144B
#define PK1 136            // B1 pitch: 272B

__device__ __forceinline__ u16 hfbits(float v) {
    __half h = __float2half_rn(v);
    return reinterpret_cast<__half_raw&>(h).x;
}
__device__ __forceinline__ float hff(u16 b) {
    __half_raw r; r.x = b;
    return __half2float(*reinterpret_cast<__half*>(&r));
}
__device__ __forceinline__ u32 pack_h2(float v0, float v1) {
    return (u32)hfbits(v0) | ((u32)hfbits(v1) << 16);
}

__device__ __forceinline__ u32 smem_u32(const void* p) {
    u32 a;
    asm("{ .reg .u64 t; cvta.to.shared.u64 t, %1; cvt.u32.u64 %0, t; }" : "=r"(a) : "l"(p));
    return a;
}
__device__ __forceinline__ void lds128(u32* v, u32 addr) {
    asm volatile("ld.shared.v4.u32 {%0,%1,%2,%3}, [%4];"
        : "=r"(v[0]), "=r"(v[1]), "=r"(v[2]), "=r"(v[3]) : "r"(addr));
}
__device__ __forceinline__ void mma16816(float* d, const u32* a, u32 b0, u32 b1) {
    asm volatile("mma.sync.aligned.m16n8k16.row.col.f32.f16.f16.f32 "
        "{%0,%1,%2,%3}, {%4,%5,%6,%7}, {%8,%9}, {%0,%1,%2,%3};"
        : "+f"(d[0]), "+f"(d[1]), "+f"(d[2]), "+f"(d[3])
        : "r"(a[0]), "r"(a[1]), "r"(a[2]), "r"(a[3]), "r"(b0), "r"(b1));
}

// MUFU.TANH (validated across all passing rounds)
__device__ __forceinline__ float tanha(float x) {
    float y; asm("tanh.approx.f32 %0, %1;" : "=f"(y) : "f"(x)); return y;
}
__device__ __forceinline__ float sigf(float x) {
    return fmaf(0.5f, tanha(0.5f * x), 0.5f);
}

// A-frag byte offsets (frag-contiguous: [tile][kb][lane][4xu32])
__device__ __forceinline__ u32 a0_off(int tile, int kb, int lane) {
    return OFF_A0 + (u32)(((tile * 4 + kb) * 32 + lane) * 16);
}
__device__ __forceinline__ u32 a1_off(int tile, int kb, int lane) {
    return OFF_A1 + (u32)(((tile * 8 + kb) * 32 + lane) * 16);
}

__global__ void __launch_bounds__(NTHR, 1)
stocklstm_mma_kernel(const float* __restrict__ x,
                     const float* __restrict__ W_ih0, const float* __restrict__ W_hh0,
                     const float* __restrict__ b_ih0, const float* __restrict__ b_hh0,
                     const float* __restrict__ W_ih1, const float* __restrict__ W_hh1,
                     const float* __restrict__ b_ih1, const float* __restrict__ b_hh1,
                     const float* __restrict__ W1,   const float* __restrict__ b1,
                     const float* __restrict__ W2,   const float* __restrict__ b2,
                     float* __restrict__ out)
{
    extern __shared__ char sm[];
    const u32 sb = smem_u32(sm);
    const int tid  = threadIdx.x;
    const int w    = tid >> 5;
    const int lane = tid & 31;
    const int grp  = lane >> 2;      // 0..7
    const int tig  = lane & 3;       // 0..3
    const int par  = grp >> 2;       // 0: lane holds (i,g); 1: (f,o)
    const int B0   = blockIdx.x * NB;

    // ---- stage A0 frags (Whh0 fp16, gate-interleaved rows: row = gate*4 + ulocal) ----
    for (int idx = tid; idx < 8192; idx += NTHR) {
        int reg = idx & 3, ln = (idx >> 2) & 31, kb = (idx >> 7) & 3;
        int tile = idx >> 9;
        int g2 = ln >> 2, t2 = ln & 3;
        int row = g2 + (reg & 1) * 8;                 // 0..15 within tile
        int col = kb * 16 + t2 * 2 + (reg >> 1) * 8;  // 0..63
        int grow = ((row >> 2) << 6) + tile * 4 + (row & 3);  // gate*64 + unit
        ((u32*)(sm + OFF_A0))[idx] =
            pack_h2(W_hh0[grow * 64 + col], W_hh0[grow * 64 + col + 1]);
    }
    // ---- stage A1 frags ([Whh1 | Wih1] along K=128) ----
    for (int idx = tid; idx < 16384; idx += NTHR) {
        int reg = idx & 3, ln = (idx >> 2) & 31, kb = (idx >> 7) & 7;
        int tile = idx >> 10;
        int g2 = ln >> 2, t2 = ln & 3;
        int row = g2 + (reg & 1) * 8;
        int col = kb * 16 + t2 * 2 + (reg >> 1) * 8;  // 0..127
        int grow = ((row >> 2) << 6) + tile * 4 + (row & 3);
        float v0, v1;
        if (col < 64) { v0 = W_hh1[grow * 64 + col];      v1 = W_hh1[grow * 64 + col + 1]; }
        else          { v0 = W_ih1[grow * 64 + col - 64]; v1 = W_ih1[grow * 64 + col - 63]; }
        ((u32*)(sm + OFF_A1))[idx] = pack_h2(v0, v1);
    }
    // ---- zero B buffers (h0 = h1 = 0), contiguous 26624B ----
    for (int idx = tid; idx < 6656; idx += NTHR)
        ((u32*)(sm + OFF_B0H))[idx] = 0u;

    // ---- per-thread constants ----
    const int tg[2] = { 2 * w, 2 * w + 1 };
    const int ga = grp >> 2;          // gate_a: 0(i) or 1(f)
    const int gc = ga + 2;            // gate_c: 2(g) or 3(o)
    const int uu[2] = { 4 * tg[0] + (grp & 3), 4 * tg[1] + (grp & 3) };

    float bA0[2], bC0[2], bA1[2], bC1[2];
    float wxA[2][5], wxC[2][5];
#pragma unroll
    for (int t2 = 0; t2 < 2; t2++) {
        int ra = ga * 64 + uu[t2], rc = gc * 64 + uu[t2];
        bA0[t2] = b_ih0[ra] + b_hh0[ra];
        bC0[t2] = b_ih0[rc] + b_hh0[rc];
        bA1[t2] = b_ih1[ra] + b_hh1[ra];
        bC1[t2] = b_ih1[rc] + b_hh1[rc];
#pragma unroll
        for (int d = 0; d < 5; d++) {
            wxA[t2][d] = W_ih0[ra * 5 + d];
            wxC[t2][d] = W_ih0[rc * 5 + d];
        }
    }

    float c0[8], c1[8], hfin[8];
#pragma unroll
    for (int p = 0; p < 8; p++) { c0[p] = 0.0f; c1[p] = 0.0f; hfin[p] = 0.0f; }

    // ---- x staging: threads 0..159 own (batch xl, feature xd) ----
    const int xl = tid / 5, xd = tid - xl * 5;
    const float* xptr = x + (size_t)(B0 + xl) * (T_LEN * D_IN) + xd;
    float xreg = 0.0f;
    if (tid < 160) {
        ((float*)(sm + OFF_XS))[xd * 32 + xl] = xptr[0];
        xreg = xptr[D_IN];
    }
    __syncthreads();

#pragma unroll 1
    for (int t = 0; t < T_LEN; t++) {
        float d[2][4][4];
        // ===== L0 D-init: bias + Wih0 @ x (fp32 scalar) =====
#pragma unroll
        for (int t2 = 0; t2 < 2; t2++)
#pragma unroll
            for (int nb = 0; nb < 4; nb++) {
                float s0 = bA0[t2], s1 = bA0[t2], s2 = bC0[t2], s3 = bC0[t2];
#pragma unroll
                for (int dd = 0; dd < 5; dd++) {
                    float2 xv = *(const float2*)((const float*)(sm + OFF_XS) + dd * 32 + nb * 8 + tig * 2);
                    s0 = fmaf(wxA[t2][dd], xv.x, s0); s1 = fmaf(wxA[t2][dd], xv.y, s1);
                    s2 = fmaf(wxC[t2][dd], xv.x, s2); s3 = fmaf(wxC[t2][dd], xv.y, s3);
                }
                d[t2][nb][0] = s0; d[t2][nb][1] = s1; d[t2][nb][2] = s2; d[t2][nb][3] = s3;
            }
        // ===== L0 mma: Whh0_f16 @ (h0_hi + h0_lo) =====
#pragma unroll
        for (int kb = 0; kb < 4; kb++) {
            u32 a0[4], a1r[4];
            lds128(a0,  sb + a0_off(tg[0], kb, lane));
            lds128(a1r, sb + a0_off(tg[1], kb, lane));
#pragma unroll
            for (int nb = 0; nb < 4; nb++) {
                u32 bo = (u32)((nb * 8 + grp) * (PK0 * 2) + (kb * 16 + tig * 2) * 2);
                u32 bh0 = *(const u32*)(sm + OFF_B0H + bo);
                u32 bh1 = *(const u32*)(sm + OFF_B0H + bo + 16);
                u32 bl0 = *(const u32*)(sm + OFF_B0L + bo);
                u32 bl1 = *(const u32*)(sm + OFF_B0L + bo + 16);
                mma16816(d[0][nb], a0,  bh0, bh1);
                mma16816(d[0][nb], a0,  bl0, bl1);
                mma16816(d[1][nb], a1r, bh0, bh1);
                mma16816(d[1][nb], a1r, bl0, bl1);
            }
        }
        __syncthreads();   // S1: all L0 B-reads (h0 old) + x reads done

        // stage x[t+1]; prefetch x[t+2]
        if (tid < 160) {
            ((float*)(sm + OFF_XS))[xd * 32 + xl] = xreg;
            int tn = (t + 2 < T_LEN) ? t + 2 : T_LEN - 1;
            xreg = xptr[tn * D_IN];
        }

        // ===== pointwise L0 (warp-local via shfl) =====
#pragma unroll
        for (int t2 = 0; t2 < 2; t2++)
#pragma unroll
            for (int nb = 0; nb < 4; nb++) {
                float d0 = d[t2][nb][0], d1 = d[t2][nb][1], d2 = d[t2][nb][2], d3 = d[t2][nb][3];
                float p0 = __shfl_xor_sync(0xFFFFFFFFu, d0, 16);
                float p1 = __shfl_xor_sync(0xFFFFFFFFu, d1, 16);
                float p2 = __shfl_xor_sync(0xFFFFFFFFu, d2, 16);
                float p3 = __shfl_xor_sync(0xFFFFFFFFu, d3, 16);
                float vi = par ? p1 : d0;
                float vf = par ? d1 : p0;
                float vg = par ? p3 : d2;
                float vo = par ? d3 : p2;
                float cc = sigf(vf) * c0[t2 * 4 + nb] + sigf(vi) * tanha(vg);
                c0[t2 * 4 + nb] = cc;
                float h = sigf(vo) * tanha(cc);
                u16 hb = hfbits(h);
                u16 lb = hfbits(h - hff(hb));
                int b = nb * 8 + tig * 2 + par;
                int u = uu[t2];
                ((u16*)(sm + OFF_B0H))[b * PK0 + u] = hb;        // next step's L0
                ((u16*)(sm + OFF_B0L))[b * PK0 + u] = lb;
                ((u16*)(sm + OFF_B1H))[b * PK1 + 64 + u] = hb;   // this step's L1 (Wih1 half)
                ((u16*)(sm + OFF_B1L))[b * PK1 + 64 + u] = lb;
            }
        __syncthreads();   // S2: h0 new visible

        // ===== L1 D-init (bias) + mma: [Whh1|Wih1]_f16 @ ([h1;h0]_hi + lo) =====
#pragma unroll
        for (int t2 = 0; t2 < 2; t2++)
#pragma unroll
            for (int nb = 0; nb < 4; nb++) {
                d[t2][nb][0] = bA1[t2]; d[t2][nb][1] = bA1[t2];
                d[t2][nb][2] = bC1[t2]; d[t2][nb][3] = bC1[t2];
            }
#pragma unroll
        for (int kb = 0; kb < 8; kb++) {
            u32 a0[4], a1r[4];
            lds128(a0,  sb + a1_off(tg[0], kb, lane));
            lds128(a1r, sb + a1_off(tg[1], kb, lane));
#pragma unroll
            for (int nb = 0; nb < 4; nb++) {
                u32 bo = (u32)((nb * 8 + grp) * (PK1 * 2) + (kb * 16 + tig * 2) * 2);
                u32 bh0 = *(const u32*)(sm + OFF_B1H + bo);
                u32 bh1 = *(const u32*)(sm + OFF_B1H + bo + 16);
                u32 bl0 = *(const u32*)(sm + OFF_B1L + bo);
                u32 bl1 = *(const u32*)(sm + OFF_B1L + bo + 16);
                mma16816(d[0][nb], a0,  bh0, bh1);
                mma16816(d[0][nb], a0,  bl0, bl1);
                mma16816(d[1][nb], a1r, bh0, bh1);
                mma16816(d[1][nb], a1r, bl0, bl1);
            }
        }
        __syncthreads();   // S3: all L1 B-reads done (h1 WAR safe)

        // ===== pointwise L1 =====
#pragma unroll
        for (int t2 = 0; t2 < 2; t2++)
#pragma unroll
            for (int nb = 0; nb < 4; nb++) {
                float d0 = d[t2][nb][0], d1 = d[t2][nb][1], d2 = d[t2][nb][2], d3 = d[t2][nb][3];
                float p0 = __shfl_xor_sync(0xFFFFFFFFu, d0, 16);
                float p1 = __shfl_xor_sync(0xFFFFFFFFu, d1, 16);
                float p2 = __shfl_xor_sync(0xFFFFFFFFu, d2, 16);
                float p3 = __shfl_xor_sync(0xFFFFFFFFu, d3, 16);
                float vi = par ? p1 : d0;
                float vf = par ? d1 : p0;
                float vg = par ? p3 : d2;
                float vo = par ? d3 : p2;
                float cc = sigf(vf) * c1[t2 * 4 + nb] + sigf(vi) * tanha(vg);
                c1[t2 * 4 + nb] = cc;
                float h = sigf(vo) * tanha(cc);
                hfin[t2 * 4 + nb] = h;
                u16 hb = hfbits(h);
                u16 lb = hfbits(h - hff(hb));
                int b = nb * 8 + tig * 2 + par;
                int u = uu[t2];
                ((u16*)(sm + OFF_B1H))[b * PK1 + u] = hb;   // h1 (Whh1 half)
                ((u16*)(sm + OFF_B1L))[b * PK1 + u] = lb;
            }
        // h1-new visibility for next step's L1 covered by next iter's S2
    }

    // ---- stash final h1 (fp32) for the MLP head (reuse B0 region: 9216B >= 8448) ----
    {
        float* scr = (float*)(sm + OFF_B0H);   // [64][33] f32
#pragma unroll
        for (int t2 = 0; t2 < 2; t2++)
#pragma unroll
            for (int nb = 0; nb < 4; nb++) {
                int b = nb * 8 + tig * 2 + par;
                scr[uu[t2] * 33 + b] = hfin[t2 * 4 + nb];
            }
    }
    __syncthreads();

    // ---- MLP head: out = W2 @ relu(W1 @ h2 + b1) + b2 ----
    if (tid < NB) {
        const float* scr = (const float*)(sm + OFF_B0H);
        float acc = b2[0];
#pragma unroll 1
        for (int u = 0; u < 32; u++) {
            float s = b1[u];
            const float* wr = W1 + u * 64;
#pragma unroll
            for (int k = 0; k < 64; k++) s += wr[k] * scr[k * 33 + tid];
            acc += W2[u] * fmaxf(s, 0.0f);
        }
        out[B0 + tid] = acc;
    }
}

extern "C" void kernel_launch(void* const* d_in, const int* in_sizes, int n_in,
                              void* d_out, int out_size)
{
    const float* x    = (const float*)d_in[0];
    const float* Wih0 = (const float*)d_in[1];
    const float* Whh0 = (const float*)d_in[2];
    const float* bih0 = (const float*)d_in[3];
    const float* bhh0 = (const float*)d_in[4];
    const float* Wih1 = (const float*)d_in[5];
    const float* Whh1 = (const float*)d_in[6];
    const float* bih1 = (const float*)d_in[7];
    const float* bhh1 = (const float*)d_in[8];
    const float* W1   = (const float*)d_in[9];
    const float* b1   = (const float*)d_in[10];
    const float* W2   = (const float*)d_in[11];
    const float* b2   = (const float*)d_in[12];
    float* out = (float*)d_out;

    cudaFuncSetAttribute(stocklstm_mma_kernel,
                         cudaFuncAttributeMaxDynamicSharedMemorySize, SMEM_BYTES);
    stocklstm_mma_kernel<<<GRID, NTHR, SMEM_BYTES>>>(
        x, Wih0, Whh0, bih0, bhh0, Wih1, Whh1, bih1, bhh1, W1, b1, W2, b2, out);
}